// round 11
// baseline (speedup 1.0000x reference)
#include <cuda_runtime.h>
#include <math.h>

// Problem constants
#define B_   2
#define L_   2048
#define D_   1024
#define H_   16
#define G_   2
#define DH_  128

// Scratch (no cudaMalloc allowed)
__device__ float g_q[(size_t)B_ * L_ * H_ * DH_];
__device__ float g_k[(size_t)B_ * L_ * G_ * DH_];
__device__ float g_v[(size_t)B_ * L_ * G_ * DH_];
__device__ float g_ctx[(size_t)B_ * L_ * H_ * DH_];

__device__ __forceinline__ unsigned f2tf(float x) {
    unsigned r;
    asm("cvt.rna.tf32.f32 %0, %1;" : "=r"(r) : "f"(x));
    return r;
}

__device__ __forceinline__ void mma_tf32(float c[4],
    unsigned a0, unsigned a1, unsigned a2, unsigned a3,
    unsigned b0, unsigned b1)
{
    asm("mma.sync.aligned.m16n8k8.row.col.f32.tf32.tf32.f32 "
        "{%0,%1,%2,%3},{%4,%5,%6,%7},{%8,%9},{%0,%1,%2,%3};"
        : "+f"(c[0]), "+f"(c[1]), "+f"(c[2]), "+f"(c[3])
        : "r"(a0), "r"(a1), "r"(a2), "r"(a3), "r"(b0), "r"(b1));
}

// ---------------------------------------------------------------------------
// TF32 GEMM body with bias, double-buffered, BK=32:
// C = A[.,K] @ B[K,N] + bias[N]
// BM=128, BN=128, 256 threads (8 warps, 4x2), warp tile 32x64.
// Dynamic smem: As[2][128][36] + Bs[2][32][136] tf32 words = 70KB.
// ---------------------------------------------------------------------------
#define APITCH 36
#define BPITCH 136
#define GS_WORDS (2 * 128 * APITCH + 2 * 32 * BPITCH)   // 17920 words

__device__ __forceinline__ void gemm_body(
    const float* __restrict__ A, const float* __restrict__ Bm,
    const float* __restrict__ bias, float* __restrict__ C,
    int N, int K, int bm, int bn, unsigned* sms)
{
    unsigned* AsB = sms;                      // [2][128][APITCH]
    unsigned* BsB = sms + 2 * 128 * APITCH;   // [2][32][BPITCH]
#define AS(bf, r, c) AsB[(bf) * 128 * APITCH + (r) * APITCH + (c)]
#define BS(bf, r, c) BsB[(bf) * 32 * BPITCH + (r) * BPITCH + (c)]

    const int tid  = threadIdx.x;
    const int warp = tid >> 5, lane = tid & 31;
    const int wm = warp >> 1, wn = warp & 1;
    const int gid = lane >> 2, tig = lane & 3;

    float acc[2][8][4];
#pragma unroll
    for (int mi = 0; mi < 2; ++mi)
#pragma unroll
        for (int ni = 0; ni < 8; ++ni)
#pragma unroll
            for (int r = 0; r < 4; ++r) acc[mi][ni][r] = 0.f;

    const int ar = tid >> 2, ac = (tid & 3) << 3;   // rows ar, ar+64; cols ac..ac+7
    const int br = tid >> 5, bc = (tid & 31) << 2;  // rows br+8*rr; cols bc..bc+3

    float4 ra[2][2], rb[4];
#pragma unroll
    for (int rr = 0; rr < 2; ++rr) {
        const float* ap = A + (size_t)(bm + ar + rr * 64) * K + ac;
        ra[rr][0] = *(const float4*)ap;
        ra[rr][1] = *(const float4*)(ap + 4);
    }
#pragma unroll
    for (int rr = 0; rr < 4; ++rr)
        rb[rr] = *(const float4*)(Bm + (size_t)(br + rr * 8) * N + bn + bc);

#pragma unroll
    for (int rr = 0; rr < 2; ++rr) {
        int r = ar + rr * 64;
#pragma unroll
        for (int hh = 0; hh < 2; ++hh) {
            uint4 u = { f2tf(ra[rr][hh].x), f2tf(ra[rr][hh].y),
                        f2tf(ra[rr][hh].z), f2tf(ra[rr][hh].w) };
            *(uint4*)&AS(0, r, ac + hh * 4) = u;
        }
    }
#pragma unroll
    for (int rr = 0; rr < 4; ++rr) {
        uint4 u = { f2tf(rb[rr].x), f2tf(rb[rr].y), f2tf(rb[rr].z), f2tf(rb[rr].w) };
        *(uint4*)&BS(0, br + rr * 8, bc) = u;
    }

    int buf = 0;
    for (int kt = 0; kt < K; kt += 32) {
        __syncthreads();
        const bool more = (kt + 32) < K;
        if (more) {
#pragma unroll
            for (int rr = 0; rr < 2; ++rr) {
                const float* ap = A + (size_t)(bm + ar + rr * 64) * K + kt + 32 + ac;
                ra[rr][0] = *(const float4*)ap;
                ra[rr][1] = *(const float4*)(ap + 4);
            }
#pragma unroll
            for (int rr = 0; rr < 4; ++rr)
                rb[rr] = *(const float4*)(Bm + (size_t)(kt + 32 + br + rr * 8) * N + bn + bc);
        }

#pragma unroll
        for (int kk = 0; kk < 4; ++kk) {
            const int k0 = kk * 8;
            unsigned a[2][4];
#pragma unroll
            for (int mi = 0; mi < 2; ++mi) {
                int row = wm * 32 + mi * 16 + gid;
                a[mi][0] = AS(buf, row, k0 + tig);
                a[mi][1] = AS(buf, row + 8, k0 + tig);
                a[mi][2] = AS(buf, row, k0 + tig + 4);
                a[mi][3] = AS(buf, row + 8, k0 + tig + 4);
            }
#pragma unroll
            for (int ni = 0; ni < 8; ++ni) {
                int col = wn * 64 + ni * 8 + gid;
                unsigned b0 = BS(buf, k0 + tig, col);
                unsigned b1 = BS(buf, k0 + tig + 4, col);
                mma_tf32(acc[0][ni], a[0][0], a[0][1], a[0][2], a[0][3], b0, b1);
                mma_tf32(acc[1][ni], a[1][0], a[1][1], a[1][2], a[1][3], b0, b1);
            }
        }

        if (more) {
            int nb = buf ^ 1;
#pragma unroll
            for (int rr = 0; rr < 2; ++rr) {
                int r = ar + rr * 64;
#pragma unroll
                for (int hh = 0; hh < 2; ++hh) {
                    uint4 u = { f2tf(ra[rr][hh].x), f2tf(ra[rr][hh].y),
                                f2tf(ra[rr][hh].z), f2tf(ra[rr][hh].w) };
                    *(uint4*)&AS(nb, r, ac + hh * 4) = u;
                }
            }
#pragma unroll
            for (int rr = 0; rr < 4; ++rr) {
                uint4 u = { f2tf(rb[rr].x), f2tf(rb[rr].y), f2tf(rb[rr].z), f2tf(rb[rr].w) };
                *(uint4*)&BS(nb, br + rr * 8, bc) = u;
            }
        }
        buf ^= 1;
    }

#pragma unroll
    for (int mi = 0; mi < 2; ++mi)
#pragma unroll
        for (int ni = 0; ni < 8; ++ni) {
            int row = bm + wm * 32 + mi * 16 + gid;
            int col = bn + wn * 64 + ni * 8 + 2 * tig;
            float bx = bias[col], by = bias[col + 1];
            float2 o0 = { acc[mi][ni][0] + bx, acc[mi][ni][1] + by };
            float2 o1 = { acc[mi][ni][2] + bx, acc[mi][ni][3] + by };
            *(float2*)(C + (size_t)row * N + col) = o0;
            *(float2*)(C + (size_t)(row + 8) * N + col) = o1;
        }
#undef AS
#undef BS
}

// Fused Q/K/V projection: grid.x = 512 + 64 + 64 = 640
__global__ void __launch_bounds__(256, 2) gemm3_kernel(
    const float* __restrict__ in_q, const float* __restrict__ Wq,
    const float* __restrict__ bq, float* __restrict__ pq,
    const float* __restrict__ in_k, const float* __restrict__ Wk,
    const float* __restrict__ bk, float* __restrict__ pk,
    const float* __restrict__ in_v, const float* __restrict__ Wv,
    const float* __restrict__ bv, float* __restrict__ pv)
{
    extern __shared__ unsigned gsm[];
    const int blk = blockIdx.x;
    if (blk < 512) {
        gemm_body(in_q, Wq, bq, pq, 2048, 1024, (blk >> 4) * 128, (blk & 15) * 128, gsm);
    } else if (blk < 576) {
        int t = blk - 512;
        gemm_body(in_k, Wk, bk, pk, 256, 1024, (t >> 1) * 128, (t & 1) * 128, gsm);
    } else {
        int t = blk - 576;
        gemm_body(in_v, Wv, bv, pv, 256, 1024, (t >> 1) * 128, (t & 1) * 128, gsm);
    }
}

__global__ void __launch_bounds__(256, 2) gemm_tf32_kernel(
    const float* __restrict__ A, const float* __restrict__ Bm,
    const float* __restrict__ bias, float* __restrict__ C,
    int M, int N, int K)
{
    extern __shared__ unsigned gsm[];
    gemm_body(A, Bm, bias, C, N, K, blockIdx.y * 128, blockIdx.x * 128, gsm);
}

// ---------------------------------------------------------------------------
// TF32 flash attention (causal, GQA). Block: 64 q rows of one head.
// 128 threads = 4 warps; warp w owns q rows w*16..+15 (full 64-wide KV).
// Q kept in registers as prebuilt A-fragments. 2 CTAs/SM co-resident.
// ---------------------------------------------------------------------------
#define KP 132
#define VP 136
#define PP 68

__global__ void __launch_bounds__(128) flash_tf32_kernel(const float* __restrict__ qes)
{
    extern __shared__ unsigned sm[];
    unsigned (*Ks)[KP] = (unsigned(*)[KP])sm;                 // [64][132]
    unsigned (*Vs)[VP] = (unsigned(*)[VP])(sm + 64 * KP);     // [64][136]
    unsigned (*Ps)[PP] = (unsigned(*)[PP])(sm + 64 * KP + 64 * VP); // [64][68]

    const int tid  = threadIdx.x;
    const int warp = tid >> 5, lane = tid & 31;
    const int gid = lane >> 2, tig = lane & 3;
    const int qt = (int)gridDim.x - 1 - (int)blockIdx.x;   // heavy tiles first
    const int bh = blockIdx.y;
    const int b = bh >> 4, h = bh & 15, g = h >> 3;

    const float scale = qes[0] * 0.08838834764831845f;  // qes / sqrt(128)

    const int d0 = (tid & 31) << 2;
    const int j0 = tid >> 5;
    const int prow = warp * 16 + gid;

    // Stage Q tile (scaled, tf32) through Ks, then build A-fragments in regs.
#pragma unroll
    for (int it = 0; it < 16; ++it) {
        int r = j0 + it * 4;
        float4 v = *(const float4*)(g_q +
            ((size_t)(b * L_ + qt * 64 + r) * H_ + h) * DH_ + d0);
        uint4 u = { f2tf(v.x * scale), f2tf(v.y * scale),
                    f2tf(v.z * scale), f2tf(v.w * scale) };
        *(uint4*)&Ks[r][d0] = u;
    }
    __syncthreads();

    unsigned aq[16][4];
#pragma unroll
    for (int kk = 0; kk < 16; ++kk) {
        aq[kk][0] = Ks[prow][kk * 8 + tig];
        aq[kk][1] = Ks[prow + 8][kk * 8 + tig];
        aq[kk][2] = Ks[prow][kk * 8 + tig + 4];
        aq[kk][3] = Ks[prow + 8][kk * 8 + tig + 4];
    }

    float m0 = -1e30f, m1 = -1e30f, l0 = 0.f, l1 = 0.f;
    float o[16][4];
#pragma unroll
    for (int ni = 0; ni < 16; ++ni)
#pragma unroll
        for (int r = 0; r < 4; ++r) o[ni][r] = 0.f;

    const int ntiles = qt + 1;

    for (int t = 0; t < ntiles; ++t) {
        __syncthreads();   // Q-frag reads (t=0) / prev-tile consumers done
        // Load K,V tile gmem -> smem (tf32)
#pragma unroll
        for (int it = 0; it < 16; ++it) {
            int j = j0 + it * 4;
            size_t base = ((size_t)(b * L_ + t * 64 + j) * G_ + g) * DH_ + d0;
            float4 kv = *(const float4*)(g_k + base);
            uint4 uk = { f2tf(kv.x), f2tf(kv.y), f2tf(kv.z), f2tf(kv.w) };
            *(uint4*)&Ks[j][d0] = uk;
            float4 vv = *(const float4*)(g_v + base);
            uint4 uv = { f2tf(vv.x), f2tf(vv.y), f2tf(vv.z), f2tf(vv.w) };
            *(uint4*)&Vs[j][d0] = uv;
        }
        __syncthreads();

        // S = Q @ K^T  (warp rows prow, prow+8; 8 n-tiles of 8)
        float s[8][4];
#pragma unroll
        for (int ni = 0; ni < 8; ++ni)
#pragma unroll
            for (int r = 0; r < 4; ++r) s[ni][r] = 0.f;

#pragma unroll
        for (int kk = 0; kk < 16; ++kk) {
            const int k0 = kk * 8;
#pragma unroll
            for (int ni = 0; ni < 8; ++ni) {
                unsigned b0 = Ks[ni * 8 + gid][k0 + tig];
                unsigned b1 = Ks[ni * 8 + gid][k0 + tig + 4];
                mma_tf32(s[ni], aq[kk][0], aq[kk][1], aq[kk][2], aq[kk][3], b0, b1);
            }
        }

        // Causal mask (diagonal tile only)
        if (t == qt) {
            const int rowg0 = qt * 64 + warp * 16 + gid;
            const int rowg1 = rowg0 + 8;
#pragma unroll
            for (int ni = 0; ni < 8; ++ni) {
                int c0 = t * 64 + ni * 8 + 2 * tig;
                if (c0 > rowg0)     s[ni][0] = -1e30f;
                if (c0 + 1 > rowg0) s[ni][1] = -1e30f;
                if (c0 > rowg1)     s[ni][2] = -1e30f;
                if (c0 + 1 > rowg1) s[ni][3] = -1e30f;
            }
        }

        // Online softmax (full row per warp; reduce over 4-lane groups)
        float rmax0 = -1e30f, rmax1 = -1e30f;
#pragma unroll
        for (int ni = 0; ni < 8; ++ni) {
            rmax0 = fmaxf(rmax0, fmaxf(s[ni][0], s[ni][1]));
            rmax1 = fmaxf(rmax1, fmaxf(s[ni][2], s[ni][3]));
        }
        rmax0 = fmaxf(rmax0, __shfl_xor_sync(0xffffffffu, rmax0, 1));
        rmax0 = fmaxf(rmax0, __shfl_xor_sync(0xffffffffu, rmax0, 2));
        rmax1 = fmaxf(rmax1, __shfl_xor_sync(0xffffffffu, rmax1, 1));
        rmax1 = fmaxf(rmax1, __shfl_xor_sync(0xffffffffu, rmax1, 2));

        float mn0 = fmaxf(m0, rmax0), mn1 = fmaxf(m1, rmax1);
        float al0 = __expf(m0 - mn0), al1 = __expf(m1 - mn1);
        float rs0 = 0.f, rs1 = 0.f;
#pragma unroll
        for (int ni = 0; ni < 8; ++ni) {
            s[ni][0] = __expf(s[ni][0] - mn0); rs0 += s[ni][0];
            s[ni][1] = __expf(s[ni][1] - mn0); rs0 += s[ni][1];
            s[ni][2] = __expf(s[ni][2] - mn1); rs1 += s[ni][2];
            s[ni][3] = __expf(s[ni][3] - mn1); rs1 += s[ni][3];
        }
        rs0 += __shfl_xor_sync(0xffffffffu, rs0, 1);
        rs0 += __shfl_xor_sync(0xffffffffu, rs0, 2);
        rs1 += __shfl_xor_sync(0xffffffffu, rs1, 1);
        rs1 += __shfl_xor_sync(0xffffffffu, rs1, 2);
        l0 = l0 * al0 + rs0; m0 = mn0;
        l1 = l1 * al1 + rs1; m1 = mn1;

#pragma unroll
        for (int ni = 0; ni < 16; ++ni) {
            o[ni][0] *= al0; o[ni][1] *= al0;
            o[ni][2] *= al1; o[ni][3] *= al1;
        }

        // P -> smem (warp-private rows, tf32)
#pragma unroll
        for (int ni = 0; ni < 8; ++ni) {
            int pc = ni * 8 + 2 * tig;
            uint2 u0 = { f2tf(s[ni][0]), f2tf(s[ni][1]) };
            uint2 u1 = { f2tf(s[ni][2]), f2tf(s[ni][3]) };
            *(uint2*)&Ps[prow][pc]     = u0;
            *(uint2*)&Ps[prow + 8][pc] = u1;
        }
        __syncwarp();

        // O += P @ V
#pragma unroll
        for (int kk = 0; kk < 8; ++kk) {
            const int k0 = kk * 8;
            unsigned a0 = Ps[prow][k0 + tig];
            unsigned a1 = Ps[prow + 8][k0 + tig];
            unsigned a2 = Ps[prow][k0 + tig + 4];
            unsigned a3 = Ps[prow + 8][k0 + tig + 4];
#pragma unroll
            for (int ni = 0; ni < 16; ++ni) {
                unsigned b0 = Vs[k0 + tig][ni * 8 + gid];
                unsigned b1 = Vs[k0 + tig + 4][ni * 8 + gid];
                mma_tf32(o[ni], a0, a1, a2, a3, b0, b1);
            }
        }
    }

    // Epilogue: O / l -> g_ctx
    const float inv0 = 1.f / l0, inv1 = 1.f / l1;
    const int r0 = qt * 64 + warp * 16 + gid;
    float* dst0 = g_ctx + ((size_t)(b * L_ + r0) * H_ + h) * DH_;
    float* dst1 = g_ctx + ((size_t)(b * L_ + r0 + 8) * H_ + h) * DH_;
#pragma unroll
    for (int ni = 0; ni < 16; ++ni) {
        int col = ni * 8 + 2 * tig;
        float2 v0 = { o[ni][0] * inv0, o[ni][1] * inv0 };
        float2 v1 = { o[ni][2] * inv1, o[ni][3] * inv1 };
        *(float2*)(dst0 + col) = v0;
        *(float2*)(dst1 + col) = v1;
    }
}

// ---------------------------------------------------------------------------
// Launcher
// ---------------------------------------------------------------------------
extern "C" void kernel_launch(void* const* d_in, const int* in_sizes, int n_in,
                              void* d_out, int out_size)
{
    const float* in_q = (const float*)d_in[0];
    const float* in_k = (const float*)d_in[1];
    const float* in_v = (const float*)d_in[2];
    const float* Wq   = (const float*)d_in[3];
    const float* bq   = (const float*)d_in[4];
    const float* Wk   = (const float*)d_in[5];
    const float* bk   = (const float*)d_in[6];
    const float* Wv   = (const float*)d_in[7];
    const float* bv   = (const float*)d_in[8];
    const float* Wo   = (const float*)d_in[9];
    const float* bo   = (const float*)d_in[10];
    const float* qes  = (const float*)d_in[11];
    float* out = (float*)d_out;

    float *pq, *pk, *pv, *pctx;
    cudaGetSymbolAddress((void**)&pq,   g_q);
    cudaGetSymbolAddress((void**)&pk,   g_k);
    cudaGetSymbolAddress((void**)&pv,   g_v);
    cudaGetSymbolAddress((void**)&pctx, g_ctx);

    const int M = B_ * L_;   // 4096
    const int gsmem = GS_WORDS * (int)sizeof(unsigned);   // 71680 B

    cudaFuncSetAttribute(gemm3_kernel,
                         cudaFuncAttributeMaxDynamicSharedMemorySize, gsmem);
    cudaFuncSetAttribute(gemm_tf32_kernel,
                         cudaFuncAttributeMaxDynamicSharedMemorySize, gsmem);

    // Fused Q/K/V projections (640 CTAs)
    gemm3_kernel<<<640, 256, gsmem>>>(in_q, Wq, bq, pq,
                                      in_k, Wk, bk, pk,
                                      in_v, Wv, bv, pv);

    const int fsmem = (64 * KP + 64 * VP + 64 * PP) * (int)sizeof(unsigned);
    cudaFuncSetAttribute(flash_tf32_kernel,
                         cudaFuncAttributeMaxDynamicSharedMemorySize, fsmem);
    flash_tf32_kernel<<<dim3(L_ / 64, B_ * H_), 128, fsmem>>>(qes);

    gemm_tf32_kernel<<<dim3(D_ / 128, M / 128), 256, gsmem>>>(
        pctx, Wo, bo, out, M, D_, H_ * DH_);
}

// round 12
// speedup vs baseline: 1.5550x; 1.5550x over previous
#include <cuda_runtime.h>
#include <math.h>

// Problem constants
#define B_   2
#define L_   2048
#define D_   1024
#define H_   16
#define G_   2
#define DH_  128

// Scratch (no cudaMalloc allowed)
__device__ float g_q[(size_t)B_ * L_ * H_ * DH_];
__device__ float g_k[(size_t)B_ * L_ * G_ * DH_];
__device__ float g_v[(size_t)B_ * L_ * G_ * DH_];
__device__ float g_ctx[(size_t)B_ * L_ * H_ * DH_];

__device__ __forceinline__ unsigned f2tf(float x) {
    unsigned r;
    asm("cvt.rna.tf32.f32 %0, %1;" : "=r"(r) : "f"(x));
    return r;
}
__device__ __forceinline__ unsigned u2tf(unsigned xb) {
    unsigned r;
    asm("cvt.rna.tf32.f32 %0, %1;" : "=r"(r) : "f"(__uint_as_float(xb)));
    return r;
}

__device__ __forceinline__ void mma_tf32(float c[4],
    unsigned a0, unsigned a1, unsigned a2, unsigned a3,
    unsigned b0, unsigned b1)
{
    asm("mma.sync.aligned.m16n8k8.row.col.f32.tf32.tf32.f32 "
        "{%0,%1,%2,%3},{%4,%5,%6,%7},{%8,%9},{%0,%1,%2,%3};"
        : "+f"(c[0]), "+f"(c[1]), "+f"(c[2]), "+f"(c[3])
        : "r"(a0), "r"(a1), "r"(a2), "r"(a3), "r"(b0), "r"(b1));
}

__device__ __forceinline__ void cp16(unsigned* smem_ptr, const float* gptr) {
    unsigned a = (unsigned)__cvta_generic_to_shared(smem_ptr);
    asm volatile("cp.async.cg.shared.global [%0], [%1], 16;" :: "r"(a), "l"(gptr));
}
#define CP_COMMIT() asm volatile("cp.async.commit_group;" ::: "memory")

// ---------------------------------------------------------------------------
// TF32 GEMM with bias, 4-stage cp.async pipeline, BK=16:
// C = A[.,K] @ B[K,N] + bias[N]
// BM=128, BN=128, 256 threads (8 warps, 4x2), warp tile 32x64.
// Smem holds raw fp32; tf32 conversion happens at fragment read.
// ---------------------------------------------------------------------------
#define GSTAGES 4
#define APITCH 20
#define BPITCH 136
#define AS_WORDS (128 * APITCH)                     // 2560
#define BS_WORDS (16 * BPITCH)                      // 2176
#define GS_WORDS (GSTAGES * (AS_WORDS + BS_WORDS))  // 18944 words = 75776 B

__device__ __forceinline__ void gemm_body(
    const float* __restrict__ A, const float* __restrict__ Bm,
    const float* __restrict__ bias, float* __restrict__ C,
    int N, int K, int bm, int bn, unsigned* sms)
{
    const int tid  = threadIdx.x;
    const int warp = tid >> 5, lane = tid & 31;
    const int wm = warp >> 1, wn = warp & 1;
    const int gid = lane >> 2, tig = lane & 3;

    const int ar = tid >> 2, ac = (tid & 3) << 2;   // A: rows ar, ar+64; col kt+ac
    const int br = tid >> 5, bc = (tid & 31) << 2;  // B: rows br, br+8; col bn+bc

    float acc[2][8][4];
#pragma unroll
    for (int mi = 0; mi < 2; ++mi)
#pragma unroll
        for (int ni = 0; ni < 8; ++ni)
#pragma unroll
            for (int r = 0; r < 4; ++r) acc[mi][ni][r] = 0.f;

    const int nst = K >> 4;

    // Prologue: issue stages 0..GSTAGES-2
#pragma unroll
    for (int s = 0; s < GSTAGES - 1; ++s) {
        unsigned* As = sms + s * (AS_WORDS + BS_WORDS);
        unsigned* Bs = As + AS_WORDS;
        int kt = s * 16;
        cp16(As + ar * APITCH + ac,        A + (size_t)(bm + ar) * K + kt + ac);
        cp16(As + (ar + 64) * APITCH + ac, A + (size_t)(bm + ar + 64) * K + kt + ac);
        cp16(Bs + br * BPITCH + bc,        Bm + (size_t)(kt + br) * N + bn + bc);
        cp16(Bs + (br + 8) * BPITCH + bc,  Bm + (size_t)(kt + br + 8) * N + bn + bc);
        CP_COMMIT();
    }

    for (int i = 0; i < nst; ++i) {
        asm volatile("cp.async.wait_group %0;" :: "n"(GSTAGES - 2) : "memory");
        __syncthreads();

        // Issue stage i+GSTAGES-1 (empty commit keeps group accounting uniform)
        int is = i + GSTAGES - 1;
        if (is < nst) {
            int slot = is & (GSTAGES - 1);
            unsigned* As = sms + slot * (AS_WORDS + BS_WORDS);
            unsigned* Bs = As + AS_WORDS;
            int kt = is * 16;
            cp16(As + ar * APITCH + ac,        A + (size_t)(bm + ar) * K + kt + ac);
            cp16(As + (ar + 64) * APITCH + ac, A + (size_t)(bm + ar + 64) * K + kt + ac);
            cp16(Bs + br * BPITCH + bc,        Bm + (size_t)(kt + br) * N + bn + bc);
            cp16(Bs + (br + 8) * BPITCH + bc,  Bm + (size_t)(kt + br + 8) * N + bn + bc);
        }
        CP_COMMIT();

        // Compute stage i
        const int slot = i & (GSTAGES - 1);
        unsigned* As = sms + slot * (AS_WORDS + BS_WORDS);
        unsigned* Bs = As + AS_WORDS;
#pragma unroll
        for (int kk = 0; kk < 2; ++kk) {
            const int k0 = kk * 8;
            unsigned a[2][4];
#pragma unroll
            for (int mi = 0; mi < 2; ++mi) {
                int row = wm * 32 + mi * 16 + gid;
                a[mi][0] = u2tf(As[row * APITCH + k0 + tig]);
                a[mi][1] = u2tf(As[(row + 8) * APITCH + k0 + tig]);
                a[mi][2] = u2tf(As[row * APITCH + k0 + tig + 4]);
                a[mi][3] = u2tf(As[(row + 8) * APITCH + k0 + tig + 4]);
            }
#pragma unroll
            for (int ni = 0; ni < 8; ++ni) {
                int col = wn * 64 + ni * 8 + gid;
                unsigned b0 = u2tf(Bs[(k0 + tig) * BPITCH + col]);
                unsigned b1 = u2tf(Bs[(k0 + tig + 4) * BPITCH + col]);
                mma_tf32(acc[0][ni], a[0][0], a[0][1], a[0][2], a[0][3], b0, b1);
                mma_tf32(acc[1][ni], a[1][0], a[1][1], a[1][2], a[1][3], b0, b1);
            }
        }
    }

#pragma unroll
    for (int mi = 0; mi < 2; ++mi)
#pragma unroll
        for (int ni = 0; ni < 8; ++ni) {
            int row = bm + wm * 32 + mi * 16 + gid;
            int col = bn + wn * 64 + ni * 8 + 2 * tig;
            float bx = bias[col], by = bias[col + 1];
            float2 o0 = { acc[mi][ni][0] + bx, acc[mi][ni][1] + by };
            float2 o1 = { acc[mi][ni][2] + bx, acc[mi][ni][3] + by };
            *(float2*)(C + (size_t)row * N + col) = o0;
            *(float2*)(C + (size_t)(row + 8) * N + col) = o1;
        }
}

// Fused Q/K/V projection: grid.x = 512 + 64 + 64 = 640
__global__ void __launch_bounds__(256, 2) gemm3_kernel(
    const float* __restrict__ in_q, const float* __restrict__ Wq,
    const float* __restrict__ bq, float* __restrict__ pq,
    const float* __restrict__ in_k, const float* __restrict__ Wk,
    const float* __restrict__ bk, float* __restrict__ pk,
    const float* __restrict__ in_v, const float* __restrict__ Wv,
    const float* __restrict__ bv, float* __restrict__ pv)
{
    extern __shared__ unsigned gsm[];
    const int blk = blockIdx.x;
    if (blk < 512) {
        gemm_body(in_q, Wq, bq, pq, 2048, 1024, (blk >> 4) * 128, (blk & 15) * 128, gsm);
    } else if (blk < 576) {
        int t = blk - 512;
        gemm_body(in_k, Wk, bk, pk, 256, 1024, (t >> 1) * 128, (t & 1) * 128, gsm);
    } else {
        int t = blk - 576;
        gemm_body(in_v, Wv, bv, pv, 256, 1024, (t >> 1) * 128, (t & 1) * 128, gsm);
    }
}

__global__ void __launch_bounds__(256, 2) gemm_tf32_kernel(
    const float* __restrict__ A, const float* __restrict__ Bm,
    const float* __restrict__ bias, float* __restrict__ C,
    int M, int N, int K)
{
    extern __shared__ unsigned gsm[];
    gemm_body(A, Bm, bias, C, N, K, blockIdx.y * 128, blockIdx.x * 128, gsm);
}

// ---------------------------------------------------------------------------
// TF32 flash attention (causal, GQA). Block: 64 q rows of one head.
// 128 threads = 4 warps; warp w owns q rows w*16..+15 (full 64-wide KV).
// Q kept in registers as prebuilt A-fragments. 2 CTAs/SM co-resident.
// (unchanged from round 9)
// ---------------------------------------------------------------------------
#define KP 132
#define VP 136
#define PP 68

__global__ void __launch_bounds__(128) flash_tf32_kernel(const float* __restrict__ qes)
{
    extern __shared__ unsigned sm[];
    unsigned (*Ks)[KP] = (unsigned(*)[KP])sm;                 // [64][132]
    unsigned (*Vs)[VP] = (unsigned(*)[VP])(sm + 64 * KP);     // [64][136]
    unsigned (*Ps)[PP] = (unsigned(*)[PP])(sm + 64 * KP + 64 * VP); // [64][68]

    const int tid  = threadIdx.x;
    const int warp = tid >> 5, lane = tid & 31;
    const int gid = lane >> 2, tig = lane & 3;
    const int qt = (int)gridDim.x - 1 - (int)blockIdx.x;   // heavy tiles first
    const int bh = blockIdx.y;
    const int b = bh >> 4, h = bh & 15, g = h >> 3;

    const float scale = qes[0] * 0.08838834764831845f;  // qes / sqrt(128)

    const int d0 = (tid & 31) << 2;
    const int j0 = tid >> 5;
    const int prow = warp * 16 + gid;

    // Stage Q tile (scaled, tf32) through Ks, then build A-fragments in regs.
#pragma unroll
    for (int it = 0; it < 16; ++it) {
        int r = j0 + it * 4;
        float4 v = *(const float4*)(g_q +
            ((size_t)(b * L_ + qt * 64 + r) * H_ + h) * DH_ + d0);
        uint4 u = { f2tf(v.x * scale), f2tf(v.y * scale),
                    f2tf(v.z * scale), f2tf(v.w * scale) };
        *(uint4*)&Ks[r][d0] = u;
    }
    __syncthreads();

    unsigned aq[16][4];
#pragma unroll
    for (int kk = 0; kk < 16; ++kk) {
        aq[kk][0] = Ks[prow][kk * 8 + tig];
        aq[kk][1] = Ks[prow + 8][kk * 8 + tig];
        aq[kk][2] = Ks[prow][kk * 8 + tig + 4];
        aq[kk][3] = Ks[prow + 8][kk * 8 + tig + 4];
    }

    float m0 = -1e30f, m1 = -1e30f, l0 = 0.f, l1 = 0.f;
    float o[16][4];
#pragma unroll
    for (int ni = 0; ni < 16; ++ni)
#pragma unroll
        for (int r = 0; r < 4; ++r) o[ni][r] = 0.f;

    const int ntiles = qt + 1;

    for (int t = 0; t < ntiles; ++t) {
        __syncthreads();   // Q-frag reads (t=0) / prev-tile consumers done
        // Load K,V tile gmem -> smem (tf32)
#pragma unroll
        for (int it = 0; it < 16; ++it) {
            int j = j0 + it * 4;
            size_t base = ((size_t)(b * L_ + t * 64 + j) * G_ + g) * DH_ + d0;
            float4 kv = *(const float4*)(g_k + base);
            uint4 uk = { f2tf(kv.x), f2tf(kv.y), f2tf(kv.z), f2tf(kv.w) };
            *(uint4*)&Ks[j][d0] = uk;
            float4 vv = *(const float4*)(g_v + base);
            uint4 uv = { f2tf(vv.x), f2tf(vv.y), f2tf(vv.z), f2tf(vv.w) };
            *(uint4*)&Vs[j][d0] = uv;
        }
        __syncthreads();

        // S = Q @ K^T  (warp rows prow, prow+8; 8 n-tiles of 8)
        float s[8][4];
#pragma unroll
        for (int ni = 0; ni < 8; ++ni)
#pragma unroll
            for (int r = 0; r < 4; ++r) s[ni][r] = 0.f;

#pragma unroll
        for (int kk = 0; kk < 16; ++kk) {
            const int k0 = kk * 8;
#pragma unroll
            for (int ni = 0; ni < 8; ++ni) {
                unsigned b0 = Ks[ni * 8 + gid][k0 + tig];
                unsigned b1 = Ks[ni * 8 + gid][k0 + tig + 4];
                mma_tf32(s[ni], aq[kk][0], aq[kk][1], aq[kk][2], aq[kk][3], b0, b1);
            }
        }

        // Causal mask (diagonal tile only)
        if (t == qt) {
            const int rowg0 = qt * 64 + warp * 16 + gid;
            const int rowg1 = rowg0 + 8;
#pragma unroll
            for (int ni = 0; ni < 8; ++ni) {
                int c0 = t * 64 + ni * 8 + 2 * tig;
                if (c0 > rowg0)     s[ni][0] = -1e30f;
                if (c0 + 1 > rowg0) s[ni][1] = -1e30f;
                if (c0 > rowg1)     s[ni][2] = -1e30f;
                if (c0 + 1 > rowg1) s[ni][3] = -1e30f;
            }
        }

        // Online softmax (full row per warp; reduce over 4-lane groups)
        float rmax0 = -1e30f, rmax1 = -1e30f;
#pragma unroll
        for (int ni = 0; ni < 8; ++ni) {
            rmax0 = fmaxf(rmax0, fmaxf(s[ni][0], s[ni][1]));
            rmax1 = fmaxf(rmax1, fmaxf(s[ni][2], s[ni][3]));
        }
        rmax0 = fmaxf(rmax0, __shfl_xor_sync(0xffffffffu, rmax0, 1));
        rmax0 = fmaxf(rmax0, __shfl_xor_sync(0xffffffffu, rmax0, 2));
        rmax1 = fmaxf(rmax1, __shfl_xor_sync(0xffffffffu, rmax1, 1));
        rmax1 = fmaxf(rmax1, __shfl_xor_sync(0xffffffffu, rmax1, 2));

        float mn0 = fmaxf(m0, rmax0), mn1 = fmaxf(m1, rmax1);
        float al0 = __expf(m0 - mn0), al1 = __expf(m1 - mn1);
        float rs0 = 0.f, rs1 = 0.f;
#pragma unroll
        for (int ni = 0; ni < 8; ++ni) {
            s[ni][0] = __expf(s[ni][0] - mn0); rs0 += s[ni][0];
            s[ni][1] = __expf(s[ni][1] - mn0); rs0 += s[ni][1];
            s[ni][2] = __expf(s[ni][2] - mn1); rs1 += s[ni][2];
            s[ni][3] = __expf(s[ni][3] - mn1); rs1 += s[ni][3];
        }
        rs0 += __shfl_xor_sync(0xffffffffu, rs0, 1);
        rs0 += __shfl_xor_sync(0xffffffffu, rs0, 2);
        rs1 += __shfl_xor_sync(0xffffffffu, rs1, 1);
        rs1 += __shfl_xor_sync(0xffffffffu, rs1, 2);
        l0 = l0 * al0 + rs0; m0 = mn0;
        l1 = l1 * al1 + rs1; m1 = mn1;

#pragma unroll
        for (int ni = 0; ni < 16; ++ni) {
            o[ni][0] *= al0; o[ni][1] *= al0;
            o[ni][2] *= al1; o[ni][3] *= al1;
        }

        // P -> smem (warp-private rows, tf32)
#pragma unroll
        for (int ni = 0; ni < 8; ++ni) {
            int pc = ni * 8 + 2 * tig;
            uint2 u0 = { f2tf(s[ni][0]), f2tf(s[ni][1]) };
            uint2 u1 = { f2tf(s[ni][2]), f2tf(s[ni][3]) };
            *(uint2*)&Ps[prow][pc]     = u0;
            *(uint2*)&Ps[prow + 8][pc] = u1;
        }
        __syncwarp();

        // O += P @ V
#pragma unroll
        for (int kk = 0; kk < 8; ++kk) {
            const int k0 = kk * 8;
            unsigned a0 = Ps[prow][k0 + tig];
            unsigned a1 = Ps[prow + 8][k0 + tig];
            unsigned a2 = Ps[prow][k0 + tig + 4];
            unsigned a3 = Ps[prow + 8][k0 + tig + 4];
#pragma unroll
            for (int ni = 0; ni < 16; ++ni) {
                unsigned b0 = Vs[k0 + tig][ni * 8 + gid];
                unsigned b1 = Vs[k0 + tig + 4][ni * 8 + gid];
                mma_tf32(o[ni], a0, a1, a2, a3, b0, b1);
            }
        }
    }

    // Epilogue: O / l -> g_ctx
    const float inv0 = 1.f / l0, inv1 = 1.f / l1;
    const int r0 = qt * 64 + warp * 16 + gid;
    float* dst0 = g_ctx + ((size_t)(b * L_ + r0) * H_ + h) * DH_;
    float* dst1 = g_ctx + ((size_t)(b * L_ + r0 + 8) * H_ + h) * DH_;
#pragma unroll
    for (int ni = 0; ni < 16; ++ni) {
        int col = ni * 8 + 2 * tig;
        float2 v0 = { o[ni][0] * inv0, o[ni][1] * inv0 };
        float2 v1 = { o[ni][2] * inv1, o[ni][3] * inv1 };
        *(float2*)(dst0 + col) = v0;
        *(float2*)(dst1 + col) = v1;
    }
}

// ---------------------------------------------------------------------------
// Launcher
// ---------------------------------------------------------------------------
extern "C" void kernel_launch(void* const* d_in, const int* in_sizes, int n_in,
                              void* d_out, int out_size)
{
    const float* in_q = (const float*)d_in[0];
    const float* in_k = (const float*)d_in[1];
    const float* in_v = (const float*)d_in[2];
    const float* Wq   = (const float*)d_in[3];
    const float* bq   = (const float*)d_in[4];
    const float* Wk   = (const float*)d_in[5];
    const float* bk   = (const float*)d_in[6];
    const float* Wv   = (const float*)d_in[7];
    const float* bv   = (const float*)d_in[8];
    const float* Wo   = (const float*)d_in[9];
    const float* bo   = (const float*)d_in[10];
    const float* qes  = (const float*)d_in[11];
    float* out = (float*)d_out;

    float *pq, *pk, *pv, *pctx;
    cudaGetSymbolAddress((void**)&pq,   g_q);
    cudaGetSymbolAddress((void**)&pk,   g_k);
    cudaGetSymbolAddress((void**)&pv,   g_v);
    cudaGetSymbolAddress((void**)&pctx, g_ctx);

    const int M = B_ * L_;   // 4096
    const int gsmem = GS_WORDS * (int)sizeof(unsigned);   // 75776 B

    cudaFuncSetAttribute(gemm3_kernel,
                         cudaFuncAttributeMaxDynamicSharedMemorySize, gsmem);
    cudaFuncSetAttribute(gemm_tf32_kernel,
                         cudaFuncAttributeMaxDynamicSharedMemorySize, gsmem);

    // Fused Q/K/V projections (640 CTAs)
    gemm3_kernel<<<640, 256, gsmem>>>(in_q, Wq, bq, pq,
                                      in_k, Wk, bk, pk,
                                      in_v, Wv, bv, pv);

    const int fsmem = (64 * KP + 64 * VP + 64 * PP) * (int)sizeof(unsigned);
    cudaFuncSetAttribute(flash_tf32_kernel,
                         cudaFuncAttributeMaxDynamicSharedMemorySize, fsmem);
    flash_tf32_kernel<<<dim3(L_ / 64, B_ * H_), 128, fsmem>>>(qes);

    gemm_tf32_kernel<<<dim3(D_ / 128, M / 128), 256, gsmem>>>(
        pctx, Wo, bo, out, M, D_, H_ * DH_);
}